// round 7
// baseline (speedup 1.0000x reference)
#include <cuda_runtime.h>

#define U 128
#define ROW_IN   (4 * U)   // 512 floats per x1 row
#define ROW_OUT  (11 * U)  // 1408 floats per output row
#define ROWS_PER_BLOCK 2
#define WARPS_PER_ROW  4
#define NWARPS (ROWS_PER_BLOCK * WARPS_PER_ROW)   // 8
#define NTHREADS (NWARPS * 32)                    // 256

// Per-warp smem: 128 floats input stage + 288 floats output stage
#define WIN_F   128
#define WOUT_F  288
#define WSMEM_F (WIN_F + WOUT_F)   // 416 floats

__global__ __launch_bounds__(NTHREADS, 4)
void ChannelWiseTensorProduct_85779086836293_kernel(
    const float* __restrict__ x1,
    const float* __restrict__ x2,
    const float* __restrict__ w,
    float* __restrict__ out)
{
    __shared__ float smem[NWARPS * WSMEM_F];

    const int t    = threadIdx.x;
    const int wid  = t >> 5;          // warp in block, 0..7
    const int lane = t & 31;
    const int rowInBlk = wid >> 2;    // 0..1
    const int wr       = wid & 3;     // warp-in-row, 0..3
    const long long b  = (long long)blockIdx.x * ROWS_PER_BLOCK + rowInBlk;

    float* swin  = smem + wid * WSMEM_F;           // 128 floats
    float* swout = swin + WIN_F;                   // 288 floats

    // ---- Warp-local input load: exactly one float4 per lane ----
    // s0 chunk: 8 float4 at x1v[8*wr + 0..8)   -> swin[0..32)
    // s1 chunk: 24 float4 at x1v[32 + 24*wr + 0..24) -> swin[32..128)
    const float4* x1v = reinterpret_cast<const float4*>(x1 + (size_t)b * ROW_IN);
    {
        int gidx, sidx;
        if (lane < 8) { gidx = 8 * wr + lane;             sidx = lane; }
        else          { gidx = 32 + 24 * wr + (lane - 8); sidx = lane; }
        reinterpret_cast<float4*>(swin)[sidx] = __ldcs(&x1v[gidx]);
    }

    // ---- x2 via shuffle broadcast (no smem, no barrier) ----
    float yv = 0.0f;
    if (lane < 4) yv = __ldcs(&x2[(size_t)b * 4 + lane]);
    const float y0  = __shfl_sync(0xffffffffu, yv, 0);
    const float y10 = __shfl_sync(0xffffffffu, yv, 1);
    const float y11 = __shfl_sync(0xffffffffu, yv, 2);
    const float y12 = __shfl_sync(0xffffffffu, yv, 3);

    __syncwarp();

    // ---- Per-channel compute: channel u = 32*wr + lane ----
    const int u = 32 * wr + lane;
    const float s0 = swin[lane];
    const float a0 = swin[32 + 3 * lane + 0];
    const float a1 = swin[32 + 3 * lane + 1];
    const float a2 = swin[32 + 3 * lane + 2];

    const float w0 = w[u];
    const float w1 = w[U + u];
    const float w2 = w[2 * U + u];
    const float w3 = w[3 * U + u];
    const float w4 = w[4 * U + u];

    const float INV_SQRT3 = 0.57735026918962576451f;
    const float INV_SQRT2 = 0.70710678118654752440f;

    float* orow = out + (size_t)b * ROW_OUT;

    // Direct coalesced scalar stores (one 128B line per warp each)
    __stcs(&orow[u], w0 * s0 * y0);
    __stcs(&orow[7 * U + u], w3 * (a0 * y10 + a1 * y11 + a2 * y12) * INV_SQRT3);

    // Stage the three 3-vector segments (96 floats each) in warp smem
    const float ws0 = w1 * s0;
    swout[3 * lane + 0] = ws0 * y10;
    swout[3 * lane + 1] = ws0 * y11;
    swout[3 * lane + 2] = ws0 * y12;

    const float wy = w2 * y0;
    swout[96 + 3 * lane + 0] = wy * a0;
    swout[96 + 3 * lane + 1] = wy * a1;
    swout[96 + 3 * lane + 2] = wy * a2;

    const float c0 = a1 * y12 - a2 * y11;
    const float c1 = a2 * y10 - a0 * y12;
    const float c2 = a0 * y11 - a1 * y10;
    const float w4s = w4 * INV_SQRT2;
    swout[192 + 3 * lane + 0] = w4s * c0;
    swout[192 + 3 * lane + 1] = w4s * c1;
    swout[192 + 3 * lane + 2] = w4s * c2;

    __syncwarp();

    // ---- Warp-local flush: 72 float4 per warp, streaming stores ----
    // Staged float4 i in [0,72): seg = i/24, off = i%24.
    // Global float4 bases (per segment, this warp): o1 -> 32 + 24*wr,
    // o2 -> 128 + 24*wr, o4 -> 256 + 24*wr.
    float4* ov = reinterpret_cast<float4*>(orow);
    const float4* sv = reinterpret_cast<const float4*>(swout);

    {
        const int i = lane;                 // seg 0 or 1
        const int seg = i / 24;
        const int off = i - seg * 24;
        const int gbase = (seg == 0) ? 32 : 128;
        __stcs(&ov[gbase + 24 * wr + off], sv[i]);
    }
    {
        const int i = lane + 32;            // seg 1 or 2
        const int seg = i / 24;
        const int off = i - seg * 24;
        const int gbase = (seg == 1) ? 128 : 256;
        __stcs(&ov[gbase + 24 * wr + off], sv[i]);
    }
    if (lane < 8) {
        const int i = lane + 64;            // seg 2
        const int off = i - 48;
        __stcs(&ov[256 + 24 * wr + off], sv[i]);
    }
}

extern "C" void kernel_launch(void* const* d_in, const int* in_sizes, int n_in,
                              void* d_out, int out_size) {
    const float* x1 = (const float*)d_in[0];
    const float* x2 = (const float*)d_in[1];
    const float* w  = (const float*)d_in[2];
    float* out = (float*)d_out;

    const int B = in_sizes[0] / ROW_IN;  // 65536
    ChannelWiseTensorProduct_85779086836293_kernel<<<B / ROWS_PER_BLOCK, NTHREADS>>>(x1, x2, w, out);
}